// round 17
// baseline (speedup 1.0000x reference)
#include <cuda_runtime.h>
#include <cuda_fp16.h>
#include <cstdint>

#define SQ 512
#define NSEQ 512
#define CM 64
#define CZ 128
#define NH 8
#define EPS 1e-5f

// Scratch (device globals: allocation-free)
__device__ float  g_w[(size_t)SQ * NH * SQ];       // raw logits [i][h][j]
__device__ __half g_whf[(size_t)SQ * NH * SQ];     // w fp16, m16n8k16 A-frag
__device__ __half g_vTf[(size_t)CM * NSEQ * SQ];   // v fp16, m16n8k16 B-frag
__device__ __half g_gTh[(size_t)CM * NSEQ * SQ];   // gate fp16 [(c*512+n)*512 + s]
__device__ __half g_o2h[(size_t)CM * NSEQ * SQ];   // gated o fp16 [(c*512+n)*512 + i]

__device__ __forceinline__ float warp_sum(float v) {
#pragma unroll
    for (int o = 16; o > 0; o >>= 1) v += __shfl_xor_sync(0xffffffffu, v, o);
    return v;
}
__device__ __forceinline__ uint32_t smem_u32(const void* p) {
    uint32_t a;
    asm("{ .reg .u64 t; cvta.to.shared.u64 t, %1; cvt.u32.u64 %0, t; }" : "=r"(a) : "l"(p));
    return a;
}
__device__ __forceinline__ float tf32rn(float x) {
    uint32_t r;
    asm("cvt.rna.tf32.f32 %0, %1;" : "=r"(r) : "f"(x));
    return __uint_as_float(r);
}
__device__ __forceinline__ void mma_tf32(float* d, const uint32_t* a,
                                         uint32_t b0, uint32_t b1) {
    asm volatile(
        "mma.sync.aligned.m16n8k8.row.col.f32.tf32.tf32.f32 "
        "{%0,%1,%2,%3}, {%4,%5,%6,%7}, {%8,%9}, {%0,%1,%2,%3};"
        : "+f"(d[0]), "+f"(d[1]), "+f"(d[2]), "+f"(d[3])
        : "r"(a[0]), "r"(a[1]), "r"(a[2]), "r"(a[3]), "r"(b0), "r"(b1));
}
__device__ __forceinline__ void mma_f16(float* d, const uint32_t* a,
                                        uint32_t b0, uint32_t b1) {
    asm volatile(
        "mma.sync.aligned.m16n8k16.row.col.f32.f16.f16.f32 "
        "{%0,%1,%2,%3}, {%4,%5,%6,%7}, {%8,%9}, {%0,%1,%2,%3};"
        : "+f"(d[0]), "+f"(d[1]), "+f"(d[2]), "+f"(d[3])
        : "r"(a[0]), "r"(a[1]), "r"(a[2]), "r"(a[3]), "r"(b0), "r"(b1));
}
#define CP_ASYNC16(dst, src) \
    asm volatile("cp.async.cg.shared.global [%0], [%1], 16;" :: "r"(dst), "l"(src))
#define CP_COMMIT() asm volatile("cp.async.commit_group;")
#define CP_WAIT(n)  asm volatile("cp.async.wait_group %0;" :: "n"(n))

// ---------------------------------------------------------------------------
// Kernel 1: b[i,h,j] = LN(z[i,j,:]) . W_b[h,:] -> g_w.  (unchanged)
// ---------------------------------------------------------------------------
__global__ __launch_bounds__(256) void bias_ln_kernel(
    const float* __restrict__ z, const float* __restrict__ lnw,
    const float* __restrict__ lnb, const float* __restrict__ Wb)
{
    __shared__ float zn[64 * 132];
    __shared__ float swb[8 * 132];
    __shared__ float bs[2 * 64 * 8];
    int tid = threadIdx.x, wid = tid >> 5, lane = tid & 31;
    int g = lane >> 2, tg = lane & 3;

    {
        int h = tid >> 5;
        *(float4*)(swb + h * 132 + lane * 4) = *(const float4*)(Wb + h * CZ + lane * 4);
    }
    float4 lw = *(const float4*)(lnw + lane * 4);
    float4 lb = *(const float4*)(lnb + lane * 4);

    size_t R0 = (size_t)blockIdx.x * 64;
#pragma unroll
    for (int rr = 0; rr < 8; ++rr) {
        int row = wid * 8 + rr;
        float4 x = *(const float4*)(z + (R0 + row) * CZ + lane * 4);
        float s = warp_sum(x.x + x.y + x.z + x.w);
        float mu = s * (1.0f / CZ);
        float d0 = x.x - mu, d1 = x.y - mu, d2 = x.z - mu, d3 = x.w - mu;
        float q = warp_sum(d0 * d0 + d1 * d1 + d2 * d2 + d3 * d3);
        float rs = rsqrtf(q * (1.0f / CZ) + EPS);
        float4 nv;
        nv.x = d0 * rs * lw.x + lb.x;
        nv.y = d1 * rs * lw.y + lb.y;
        nv.z = d2 * rs * lw.z + lb.z;
        nv.w = d3 * rs * lw.w + lb.w;
        *(float4*)(zn + row * 132 + lane * 4) = nv;
    }
    __syncthreads();

    {
        int wmt = wid & 3, kh = wid >> 2;
        float acc[4] = {0.f, 0.f, 0.f, 0.f};
#pragma unroll
        for (int ks = 0; ks < 8; ++ks) {
            int k = kh * 64 + ks * 8;
            float a0 = zn[(wmt * 16 + g) * 132 + k + tg];
            float a1 = zn[(wmt * 16 + g + 8) * 132 + k + tg];
            float a2 = zn[(wmt * 16 + g) * 132 + k + tg + 4];
            float a3 = zn[(wmt * 16 + g + 8) * 132 + k + tg + 4];
            uint32_t ah[4], al[4];
            float h0 = tf32rn(a0), h1 = tf32rn(a1), h2 = tf32rn(a2), h3 = tf32rn(a3);
            ah[0] = __float_as_uint(h0); ah[1] = __float_as_uint(h1);
            ah[2] = __float_as_uint(h2); ah[3] = __float_as_uint(h3);
            al[0] = __float_as_uint(tf32rn(a0 - h0));
            al[1] = __float_as_uint(tf32rn(a1 - h1));
            al[2] = __float_as_uint(tf32rn(a2 - h2));
            al[3] = __float_as_uint(tf32rn(a3 - h3));
            float b0 = swb[g * 132 + k + tg];
            float b1 = swb[g * 132 + k + tg + 4];
            float bh0 = tf32rn(b0), bh1 = tf32rn(b1);
            uint32_t ubh0 = __float_as_uint(bh0), ubh1 = __float_as_uint(bh1);
            uint32_t ubl0 = __float_as_uint(tf32rn(b0 - bh0));
            uint32_t ubl1 = __float_as_uint(tf32rn(b1 - bh1));
            mma_tf32(acc, ah, ubh0, ubh1);
            mma_tf32(acc, al, ubh0, ubh1);
            mma_tf32(acc, ah, ubl0, ubl1);
        }
        int base = kh * 512 + (wmt * 16 + g) * 8 + 2 * tg;
        bs[base] = acc[0];
        bs[base + 1] = acc[1];
        bs[base + 64] = acc[2];
        bs[base + 65] = acc[3];
    }
    __syncthreads();
    {
        int h = tid >> 6, row = tid & 63;
        float v = bs[row * 8 + h] + bs[512 + row * 8 + h];
        float v2 = bs[row * 8 + h + 4] + bs[512 + row * 8 + h + 4];
        int i = (int)(R0 >> 9), j0 = (int)(R0 & 511);
        g_w[(size_t)i * 4096 + h * 512 + j0 + row] = v;
        g_w[(size_t)i * 4096 + (h + 4) * 512 + j0 + row] = v2;
    }
}

// ---------------------------------------------------------------------------
// Kernel 2: softmax over j; fp16 A-frag slabs.  (unchanged, occ 2)
// ---------------------------------------------------------------------------
#define SMX_SMEMB (8704 * 4)
__global__ __launch_bounds__(256, 2) void softmax_kernel()
{
    extern __shared__ float sx[];
    float* smh = sx;
    int tid = threadIdx.x;
    int row = tid >> 4, l = tid & 15;
    int I = blockIdx.x >> 3, h = blockIdx.x & 7;
    const float* src = g_w + ((size_t)(I * 16 + row)) * 4096 + h * 512;

    float w[32];
    float mx = -1e30f;
#pragma unroll
    for (int jj = 0; jj < 32; ++jj) {
        w[jj] = src[jj * 16 + l];
        mx = fmaxf(mx, w[jj]);
    }
#pragma unroll
    for (int o = 8; o > 0; o >>= 1) mx = fmaxf(mx, __shfl_xor_sync(0xffffffffu, mx, o));
    float sum = 0.f;
#pragma unroll
    for (int jj = 0; jj < 32; ++jj) {
        w[jj] = __expf(w[jj] - mx);
        sum += w[jj];
    }
#pragma unroll
    for (int o = 8; o > 0; o >>= 1) sum += __shfl_xor_sync(0xffffffffu, sum, o);
    float inv = 1.0f / sum;
#pragma unroll
    for (int jj = 0; jj < 32; ++jj) {
        int j = jj * 16 + l;
        smh[j * 17 + row] = w[jj] * inv;
    }
    __syncthreads();

    __half* dh = g_whf + (size_t)(I * 8 + h) * 8192;
#pragma unroll
    for (int it = 0; it < 4; ++it) {
        int u = it * 256 + tid;
        int jg16 = u >> 5, lane = u & 31;
        int gg = lane >> 2, tt = lane & 3;
        __half2 hs[4];
#pragma unroll
        for (int r = 0; r < 4; ++r) {
            int il = gg + (r & 1) * 8;
            int j0 = jg16 * 16 + ((r >> 1) * 8) + 2 * tt;
            hs[r] = __floats2half2_rn(smh[j0 * 17 + il], smh[(j0 + 1) * 17 + il]);
        }
        *(uint4*)(dh + (size_t)u * 8) = *(uint4*)hs;
    }
}

// ---------------------------------------------------------------------------
// Kernel 3: vg, retiled: block = 8 n x 16 s (row = s_loc*8 + n_loc).
// LN(m) -> fp16 mma -> vT (full coalesced B-frag slabs) + gate.  occ 2.
// ---------------------------------------------------------------------------
#define VG_SMEMB (16896 * 4)

__global__ __launch_bounds__(256, 2) void vg_kernel(
    const float* __restrict__ m, const float* __restrict__ lnw,
    const float* __restrict__ lnb, const float* __restrict__ Wv,
    const float* __restrict__ Wg)
{
    extern __shared__ float sm[];
    __half* Ash = (__half*)sm;                 // [128][72]
    __half* Bsh = Ash + 128 * 72;              // [128][72]
    int tid = threadIdx.x, wid = tid >> 5, lane = tid & 31;
    int g = lane >> 2, tg = lane & 3;
    int n0 = blockIdx.x * 8, s0 = blockIdx.y * 16;

    {   // phase 1: LN -> fp16 rows; weights -> fp16 rows
        int row = tid >> 1, half = tid & 1;       // row = s_loc*8 + n_loc
        int s_loc = row >> 3, n_loc = row & 7;
        const float* src = m + ((size_t)(s0 + s_loc) * 512 + n0 + n_loc) * CM + half * 32;
        float v[32];
        float s = 0.f, q = 0.f;
#pragma unroll
        for (int qd = 0; qd < 8; ++qd) {
            float4 a = *(const float4*)(src + qd * 4);
            v[qd * 4 + 0] = a.x; v[qd * 4 + 1] = a.y;
            v[qd * 4 + 2] = a.z; v[qd * 4 + 3] = a.w;
            s += a.x + a.y + a.z + a.w;
            q += a.x * a.x + a.y * a.y + a.z * a.z + a.w * a.w;
        }
        s += __shfl_xor_sync(0xffffffffu, s, 1);
        q += __shfl_xor_sync(0xffffffffu, q, 1);
        float mu = s * (1.0f / CM);
        float var = q * (1.0f / CM) - mu * mu;
        float rs = rsqrtf(var + EPS);
#pragma unroll
        for (int qd = 0; qd < 8; ++qd) {
            int kq = half * 8 + qd;
            float xs[4];
#pragma unroll
            for (int t = 0; t < 4; ++t) {
                int k = kq * 4 + t;
                xs[t] = (v[qd * 4 + t] - mu) * rs * __ldg(lnw + k) + __ldg(lnb + k);
            }
            __half2 h0 = __floats2half2_rn(xs[0], xs[1]);
            __half2 h1 = __floats2half2_rn(xs[2], xs[3]);
            uint2 pk;
            pk.x = *(uint32_t*)&h0;
            pk.y = *(uint32_t*)&h1;
            *(uint2*)(Ash + row * 72 + kq * 4) = pk;
        }
        const float* wsrc = (row < 64) ? (Wv + row * 64) : (Wg + (row - 64) * 64);
#pragma unroll
        for (int qd = 0; qd < 8; ++qd) {
            int kq = half * 8 + qd;
            float4 a = *(const float4*)(wsrc + kq * 4);
            __half2 h0 = __floats2half2_rn(a.x, a.y);
            __half2 h1 = __floats2half2_rn(a.z, a.w);
            uint2 pk;
            pk.x = *(uint32_t*)&h0;
            pk.y = *(uint32_t*)&h1;
            *(uint2*)(Bsh + row * 72 + kq * 4) = pk;
        }
    }
    __syncthreads();

    // phase 2: fp16 mma (row-content agnostic)
    int wi = (wid & 3) * 32, wn = (wid >> 2) * 64;
    float acc[2][8][4];
#pragma unroll
    for (int mt = 0; mt < 2; ++mt)
#pragma unroll
        for (int nt = 0; nt < 8; ++nt)
#pragma unroll
            for (int r = 0; r < 4; ++r) acc[mt][nt][r] = 0.f;

#pragma unroll
    for (int ks = 0; ks < 4; ++ks) {
        int kb = ks * 16 + 2 * tg;
        uint32_t a[2][4];
#pragma unroll
        for (int mt = 0; mt < 2; ++mt) {
            int r0 = wi + mt * 16 + g;
            a[mt][0] = *(const uint32_t*)(Ash + r0 * 72 + kb);
            a[mt][1] = *(const uint32_t*)(Ash + (r0 + 8) * 72 + kb);
            a[mt][2] = *(const uint32_t*)(Ash + r0 * 72 + kb + 8);
            a[mt][3] = *(const uint32_t*)(Ash + (r0 + 8) * 72 + kb + 8);
        }
#pragma unroll
        for (int nt = 0; nt < 8; ++nt) {
            int n0f = wn + nt * 8 + g;
            uint32_t b0 = *(const uint32_t*)(Bsh + n0f * 72 + kb);
            uint32_t b1 = *(const uint32_t*)(Bsh + n0f * 72 + kb + 8);
#pragma unroll
            for (int mt = 0; mt < 2; ++mt)
                mma_f16(acc[mt][nt], a[mt], b0, b1);
        }
    }
    __syncthreads();

    // phase 3: epilogue (Cs/Cg2 [col c][row])
    float* Cs = sm;
    float* Cg2 = sm + 8448;
#pragma unroll
    for (int mt = 0; mt < 2; ++mt) {
        int r = wi + mt * 16 + g;
#pragma unroll
        for (int nt = 0; nt < 8; ++nt) {
            int col = wn + nt * 8 + 2 * tg;
            if (wid < 4) {
                Cs[col * 132 + r]            = acc[mt][nt][0];
                Cs[(col + 1) * 132 + r]      = acc[mt][nt][1];
                Cs[col * 132 + r + 8]        = acc[mt][nt][2];
                Cs[(col + 1) * 132 + r + 8]  = acc[mt][nt][3];
            } else {
                int cl = col - 64;
                Cg2[cl * 132 + r]            = 1.0f / (1.0f + __expf(-acc[mt][nt][0]));
                Cg2[(cl + 1) * 132 + r]      = 1.0f / (1.0f + __expf(-acc[mt][nt][1]));
                Cg2[cl * 132 + r + 8]        = 1.0f / (1.0f + __expf(-acc[mt][nt][2]));
                Cg2[(cl + 1) * 132 + r + 8]  = 1.0f / (1.0f + __expf(-acc[mt][nt][3]));
            }
        }
    }
    __syncthreads();
    // vT emission: full coalesced slabs.  lane = gpos*4+tt; halves =
    // {s=2tt,2tt+1,2tt+8,2tt+9} with row = s_loc*8 + gpos.
#pragma unroll
    for (int it = 0; it < 8; ++it) {
        int u = it * 256 + tid;
        int c = u >> 5, ln = u & 31;
        int gpos = ln >> 2, tt = ln & 3;
        __half2 p0 = __floats2half2_rn(Cs[c * 132 + (2 * tt) * 8 + gpos],
                                       Cs[c * 132 + (2 * tt + 1) * 8 + gpos]);
        __half2 p1 = __floats2half2_rn(Cs[c * 132 + (2 * tt + 8) * 8 + gpos],
                                       Cs[c * 132 + (2 * tt + 9) * 8 + gpos]);
        int d = c & 7, hh = c >> 3;
        size_t off = ((size_t)(hh * 512 + d * 64 + blockIdx.x)) * 4096
                   + (size_t)blockIdx.y * 128 + ln * 4;
        uint2 pk;
        pk.x = *(uint32_t*)&p0;
        pk.y = *(uint32_t*)&p1;
        *(uint2*)(g_vTf + off) = pk;
    }
    // gate emission: per (c, n_loc): 16 s halves = two uint4
#pragma unroll
    for (int it = 0; it < 4; ++it) {
        int u = it * 256 + tid;
        int c = u >> 4, rem = u & 15;
        int n_loc = rem >> 1, hf16 = rem & 1;
        __half2 hs[4];
#pragma unroll
        for (int p = 0; p < 4; ++p) {
            int st0 = hf16 * 8 + p * 2;
            hs[p] = __floats2half2_rn(Cg2[c * 132 + st0 * 8 + n_loc],
                                      Cg2[c * 132 + (st0 + 1) * 8 + n_loc]);
        }
        *(uint4*)(g_gTh + ((size_t)c * 512 + n0 + n_loc) * 512 + s0 + hf16 * 8)
            = *(uint4*)hs;
    }
}

// ---------------------------------------------------------------------------
// Kernel 4: pwa fp16 mma, 256 thr, M=128 x N=128, 2 CTAs/SM, kc=64.
// Stage: A 16KB | B 16KB = 32KB; 3 stages = 96KB (peak; epi 67.6KB aliased).
// ---------------------------------------------------------------------------
#define PW_STGH 16384
#define PW_STGB 32768
#define PW_SMEMB 98304

__device__ __forceinline__ void pw_ldstage(uint32_t sb, int tid,
                                           const __half* Ah_g, const __half* Bg,
                                           int chunk)
{
    int jg0 = chunk * 4;
#pragma unroll
    for (int it = 0; it < 4; ++it) {       // A: 1024 x 16B (8 Igl x 4 jg16)
        int t = it * 256 + tid;
        int Igl = t >> 7, rem = t & 127;
        int jgl = rem >> 5, lane = rem & 31;
        size_t src = (size_t)Igl * 65536 + (size_t)(jg0 + jgl) * 256 + lane * 8;
        CP_ASYNC16(sb + (uint32_t)t * 16, Ah_g + src);
    }
#pragma unroll
    for (int it = 0; it < 4; ++it) {       // B: 1024 x 16B (16 ndgl x 4 jg16)
        int t = it * 256 + tid;
        int ndgl = t >> 6, rem = t & 63;
        int jgl = rem >> 4, lp = rem & 15;
        size_t src = (size_t)ndgl * 4096 + (size_t)(jg0 + jgl) * 128 + lp * 8;
        CP_ASYNC16(sb + 16384 + (uint32_t)t * 16, Bg + src);
    }
}

__global__ __launch_bounds__(256, 2) void pwa_mma_kernel()
{
    extern __shared__ float sm[];
    uint32_t sbase = smem_u32(sm);
    int tid = threadIdx.x, wid = tid >> 5, lane = tid & 31;
    int g = lane >> 2, tg = lane & 3;
    int h = blockIdx.z;
    int i0 = blockIdx.y * 128;
    int nd0 = blockIdx.x * 128;
    const __half* Ah_g = g_whf + (size_t)((i0 >> 4) * 8 + h) * 8192;
    const __half* Bg   = g_vTf + (size_t)(h * 512 + (nd0 >> 3)) * 4096;

    int iw = (wid & 3) * 2;
    int nw = (wid >> 2) * 8;
    int wi = (wid & 3) * 32, wn = (wid >> 2) * 64;

    float acc[2][8][4];
#pragma unroll
    for (int mt = 0; mt < 2; ++mt)
#pragma unroll
        for (int nt = 0; nt < 8; ++nt)
#pragma unroll
            for (int r = 0; r < 4; ++r) acc[mt][nt][r] = 0.f;

    pw_ldstage(sbase, tid, Ah_g, Bg, 0);
    CP_COMMIT();
    pw_ldstage(sbase + PW_STGB, tid, Ah_g, Bg, 1);
    CP_COMMIT();

    for (int c = 0; c < 8; ++c) {
        int slot = c % 3;
        if (c + 2 < 8) {
            pw_ldstage(sbase + ((c + 2) % 3) * PW_STGB, tid, Ah_g, Bg, c + 2);
            CP_COMMIT();
            CP_WAIT(2);
        } else if (c + 1 < 8) {
            CP_WAIT(1);
        } else {
            CP_WAIT(0);
        }
        __syncthreads();

        const __half* Ah2 = (const __half*)sm + (size_t)slot * PW_STGH;
        const __half* Bh2 = Ah2 + 8192;
#pragma unroll
        for (int kk = 0; kk < 4; ++kk) {
            uint4 av[2];
#pragma unroll
            for (int mt = 0; mt < 2; ++mt) {
                int Igl = iw + mt;
                av[mt] = *(const uint4*)(Ah2 + (size_t)((Igl * 4 + kk) * 32 + lane) * 8);
            }
#pragma unroll
            for (int nt = 0; nt < 8; ++nt) {
                int ndgl = nw + nt;
                uint2 bv = *(const uint2*)(Bh2 + (size_t)((ndgl * 4 + kk) * 32 + lane) * 4);
#pragma unroll
                for (int mt = 0; mt < 2; ++mt)
                    mma_f16(acc[mt][nt], (const uint32_t*)&av[mt], bv.x, bv.y);
            }
        }
        __syncthreads();
    }

    // epilogue: stage C [col 128][132 rows], fp16 gate-multiply, fp16 store
    float* Cs = sm;
#pragma unroll
    for (int mt = 0; mt < 2; ++mt) {
        int r = wi + mt * 16 + g;
#pragma unroll
        for (int nt = 0; nt < 8; ++nt) {
            int col = wn + nt * 8 + 2 * tg;
            Cs[col * 132 + r]            = acc[mt][nt][0];
            Cs[(col + 1) * 132 + r]      = acc[mt][nt][1];
            Cs[col * 132 + r + 8]        = acc[mt][nt][2];
            Cs[(col + 1) * 132 + r + 8]  = acc[mt][nt][3];
        }
    }
    __syncthreads();
    size_t obase = ((size_t)h * 4096 + nd0) * 512 + i0;
#pragma unroll
    for (int it = 0; it < 16; ++it) {
        int idx = it * 256 + tid;
        int col = idx >> 5, rq = idx & 31;
        float4 ov = *(const float4*)(Cs + col * 132 + rq * 4);
        const __half2* gp = (const __half2*)(g_gTh + obase + (size_t)col * 512 + rq * 4);
        float2 g0 = __half22float2(gp[0]);
        float2 g1 = __half22float2(gp[1]);
        __half2 r0 = __floats2half2_rn(ov.x * g0.x, ov.y * g0.y);
        __half2 r1 = __floats2half2_rn(ov.z * g1.x, ov.w * g1.y);
        uint2 pk;
        pk.x = *(uint32_t*)&r0;
        pk.y = *(uint32_t*)&r1;
        *(uint2*)(g_o2h + obase + (size_t)col * 512 + rq * 4) = pk;
    }
}

// ---------------------------------------------------------------------------
// Kernel 5: outT = Wout(fp16) @ G(fp16) via m16n8k16 mma.  (unchanged, occ 2)
// ---------------------------------------------------------------------------
#define OUT_SMEMB 44032
__global__ __launch_bounds__(256, 2) void out_kernel(
    const float* __restrict__ Wout, float* __restrict__ out)
{
    extern __shared__ char so[];
    __half* Gt = (__half*)so;
    __half* Wh = (__half*)(so + 34816);
    float*  Ds = (float*)so;
    int tid = threadIdx.x, wid = tid >> 5, lane = tid & 31;
    int g = lane >> 2, tg = lane & 3;
    int n = blockIdx.x & 511, s0 = (blockIdx.x >> 9) * 128;

#pragma unroll
    for (int it = 0; it < 4; ++it) {
        int idx = it * 256 + tid;
        int co = idx >> 4, q = idx & 15;
        float4 a = *(const float4*)(Wout + co * 64 + q * 4);
        __half2 h0 = __floats2half2_rn(a.x, a.y);
        __half2 h1 = __floats2half2_rn(a.z, a.w);
        uint2 pk;
        pk.x = *(uint32_t*)&h0;
        pk.y = *(uint32_t*)&h1;
        *(uint2*)(Wh + co * 72 + q * 4) = pk;
    }
#pragma unroll
    for (int it = 0; it < 8; ++it) {
        int idx = it * 256 + tid;
        int c = idx >> 5, sq = idx & 31;
        uint2 v = *(const uint2*)(g_o2h + ((size_t)c * 512 + n) * 512 + s0 + sq * 4);
        const __half* hv = (const __half*)&v;
        Gt[(sq * 4 + 0) * 72 + c] = hv[0];
        Gt[(sq * 4 + 1) * 72 + c] = hv[1];
        Gt[(sq * 4 + 2) * 72 + c] = hv[2];
        Gt[(sq * 4 + 3) * 72 + c] = hv[3];
    }
    __syncthreads();

    float acc[4][2][4];
#pragma unroll
    for (int mt = 0; mt < 4; ++mt)
#pragma unroll
        for (int nt = 0; nt < 2; ++nt)
#pragma unroll
            for (int r = 0; r < 4; ++r) acc[mt][nt][r] = 0.f;

#pragma unroll
    for (int ks = 0; ks < 4; ++ks) {
        uint32_t a[4][4];
#pragma unroll
        for (int mt = 0; mt < 4; ++mt) {
            const uint32_t* w0 = (const uint32_t*)(Wh + (mt * 16 + g) * 72);
            const uint32_t* w1 = (const uint32_t*)(Wh + (mt * 16 + g + 8) * 72);
            a[mt][0] = w0[ks * 8 + tg];
            a[mt][1] = w1[ks * 8 + tg];
            a[mt][2] = w0[ks * 8 + tg + 4];
            a[mt][3] = w1[ks * 8 + tg + 4];
        }
#pragma unroll
        for (int nt = 0; nt < 2; ++nt) {
            int col = (wid * 2 + nt) * 8 + g;
            const uint32_t* gr = (const uint32_t*)(Gt + col * 72);
            uint32_t b0 = gr[ks * 8 + tg];
            uint32_t b1 = gr[ks * 8 + tg + 4];
#pragma unroll
            for (int mt = 0; mt < 4; ++mt)
                mma_f16(acc[mt][nt], a[mt], b0, b1);
        }
    }
    __syncthreads();

#pragma unroll
    for (int mt = 0; mt < 4; ++mt) {
        int row = mt * 16 + g;
#pragma unroll
        for (int nt = 0; nt < 2; ++nt) {
            int col = (wid * 2 + nt) * 8 + 2 * tg;
            Ds[col * 68 + row]           = acc[mt][nt][0];
            Ds[(col + 1) * 68 + row]     = acc[mt][nt][1];
            Ds[col * 68 + row + 8]       = acc[mt][nt][2];
            Ds[(col + 1) * 68 + row + 8] = acc[mt][nt][3];
        }
    }
    __syncthreads();
#pragma unroll
    for (int it = 0; it < 8; ++it) {
        int idx = it * 256 + tid;
        int s = idx >> 4, cq = idx & 15;
        *(float4*)(out + ((size_t)(s0 + s) * 512 + n) * CM + cq * 4) =
            *(const float4*)(Ds + s * 68 + cq * 4);
    }
}

// ---------------------------------------------------------------------------
extern "C" void kernel_launch(void* const* d_in, const int* in_sizes, int n_in,
                              void* d_out, int out_size)
{
    const float* m    = (const float*)d_in[0];
    const float* z    = (const float*)d_in[1];
    const float* lnmw = (const float*)d_in[2];
    const float* lnmb = (const float*)d_in[3];
    const float* lnzw = (const float*)d_in[4];
    const float* lnzb = (const float*)d_in[5];
    const float* Wv   = (const float*)d_in[6];
    const float* Wb   = (const float*)d_in[7];
    const float* Wg   = (const float*)d_in[8];
    const float* Wout = (const float*)d_in[9];
    float* out = (float*)d_out;

    cudaFuncSetAttribute(pwa_mma_kernel,
                         cudaFuncAttributeMaxDynamicSharedMemorySize, PW_SMEMB);
    cudaFuncSetAttribute(vg_kernel,
                         cudaFuncAttributeMaxDynamicSharedMemorySize, VG_SMEMB);
    cudaFuncSetAttribute(softmax_kernel,
                         cudaFuncAttributeMaxDynamicSharedMemorySize, SMX_SMEMB);
    cudaFuncSetAttribute(out_kernel,
                         cudaFuncAttributeMaxDynamicSharedMemorySize, OUT_SMEMB);

    bias_ln_kernel<<<SQ * SQ / 64, 256>>>(z, lnzw, lnzb, Wb);
    softmax_kernel<<<(SQ / 16) * NH, 256, SMX_SMEMB>>>();
    vg_kernel<<<dim3(64, 32), 256, VG_SMEMB>>>(m, lnmw, lnmb, Wv, Wg);
    dim3 gD(32, 4, NH);
    pwa_mma_kernel<<<gD, 256, PW_SMEMB>>>();
    out_kernel<<<SQ * NSEQ / 128, 256, OUT_SMEMB>>>(Wout, out);
}